// round 10
// baseline (speedup 1.0000x reference)
#include <cuda_runtime.h>
#include <cstdint>

// DETR-style postprocess:
//   logits [256,1000,80] f32, boxes [256,1000,4] f32 (cxcywh)
//   -> labels [256,300], boxes_xyxy [256,300,4], scores [256,300]
// Output concatenated flat f32: labels | boxes | scores. (verified R3)

#define BATCH      256
#define QQ         1000
#define CC         80
#define NELEM      80000      // QQ*CC per batch
#define NV4        20000      // NELEM/4 (float4 units)
#define KTOP       300
#define CAP        4096
#define NBINS      2048
#define T_STATIC   2.5f

// filter decomposition: 4 segments per batch, 256 threads each
#define SEGS       4
#define FTHREADS   256
#define SEG_F4     (NV4 / SEGS)          // 5000 float4 per segment
#define FULL_IT    4                     // 4 x 1024 float4
#define TAIL_F4    (SEG_F4 - FULL_IT * 4 * FTHREADS)   // 904
#define TAIL_GUARD (TAIL_F4 - 3 * FTHREADS)            // 136

#define RTHREADS   512

#define LBL_OFF    0
#define BOX_OFF    (BATCH * KTOP)            // 76800
#define SCR_OFF    (BATCH * KTOP * 5)        // 384000

// Global scratch (zero-initialized at module load; rank kernel re-zeros g_cnt)
__device__ unsigned long long g_pack[BATCH][CAP];
__device__ int g_cnt[BATCH];

// Monotone float->uint key (ascending order preserved)
__device__ __forceinline__ unsigned f2key(float x) {
    unsigned b = __float_as_uint(x);
    return (b & 0x80000000u) ? ~b : (b | 0x80000000u);
}
__device__ __forceinline__ float key2f(unsigned k) {
    unsigned b = (k & 0x80000000u) ? (k & 0x7FFFFFFFu) : ~k;
    return __uint_as_float(b);
}

// ------------------------------------------------------------------
// Kernel 1: stream logits, predicated direct push of candidates (>T)
// ------------------------------------------------------------------
__global__ __launch_bounds__(FTHREADS)
void filter_kernel(const float* __restrict__ logits)
{
    const int b   = blockIdx.y;
    const int seg = blockIdx.x * SEG_F4;
    const int tid = threadIdx.x;
    const float4* lg4 = (const float4*)(logits + (size_t)b * NELEM);

    #pragma unroll 1
    for (int it = 0; it < FULL_IT; it++) {
        int base = seg + it * (4 * FTHREADS) + tid;
        // 4 independent front-batched loads (MLP=4)
        float4 v0 = lg4[base];
        float4 v1 = lg4[base + FTHREADS];
        float4 v2 = lg4[base + 2 * FTHREADS];
        float4 v3 = lg4[base + 3 * FTHREADS];

        float vv[16] = {v0.x, v0.y, v0.z, v0.w,  v1.x, v1.y, v1.z, v1.w,
                        v2.x, v2.y, v2.z, v2.w,  v3.x, v3.y, v3.z, v3.w};
        #pragma unroll
        for (int k = 0; k < 16; k++) {
            if (vv[k] > T_STATIC) {
                int pos = atomicAdd(&g_cnt[b], 1);
                if (pos < CAP) {
                    unsigned idx = (unsigned)((base + (k >> 2) * FTHREADS) * 4 + (k & 3));
                    g_pack[b][pos] = ((unsigned long long)f2key(vv[k]) << 32)
                                     | (unsigned long long)(~idx);
                }
            }
        }
    }
    {   // tail: 904 float4 -> 3 full loads + 1 guarded
        int base = seg + FULL_IT * (4 * FTHREADS) + tid;
        float4 v0 = lg4[base];
        float4 v1 = lg4[base + FTHREADS];
        float4 v2 = lg4[base + 2 * FTHREADS];
        float4 v3 = make_float4(-1e30f, -1e30f, -1e30f, -1e30f);
        if (tid < TAIL_GUARD) v3 = lg4[base + 3 * FTHREADS];

        float vv[16] = {v0.x, v0.y, v0.z, v0.w,  v1.x, v1.y, v1.z, v1.w,
                        v2.x, v2.y, v2.z, v2.w,  v3.x, v3.y, v3.z, v3.w};
        #pragma unroll
        for (int k = 0; k < 16; k++) {
            if (vv[k] > T_STATIC) {
                int pos = atomicAdd(&g_cnt[b], 1);
                if (pos < CAP) {
                    unsigned idx = (unsigned)((base + (k >> 2) * FTHREADS) * 4 + (k & 3));
                    g_pack[b][pos] = ((unsigned long long)f2key(vv[k]) << 32)
                                     | (unsigned long long)(~idx);
                }
            }
        }
    }
}

// ------------------------------------------------------------------
// Kernel 2: per-batch exact rank of candidates + output (+exact fallback)
// ------------------------------------------------------------------
__global__ __launch_bounds__(RTHREADS)
void rank_kernel(const float* __restrict__ logits,
                 const float* __restrict__ boxes,
                 float* __restrict__ out)
{
    __shared__ __align__(16) unsigned long long s_pack[CAP];
    __shared__ unsigned s_hist[NBINS];   // fallback only
    __shared__ int s_cnt;
    __shared__ int s_b1, s_gt, s_b2;

    const int b   = blockIdx.x;
    const int tid = threadIdx.x;
    const float4* lg4 = (const float4*)(logits + (size_t)b * NELEM);

    const int M0 = g_cnt[b];
    int M = min(M0, CAP);

    // candidates global -> shared (L2-hot, ~4KB)
    for (int i = tid; i < M; i += RTHREADS)
        s_pack[i] = g_pack[b][i];

    // reset the counter for the next graph replay
    if (tid == 0) g_cnt[b] = 0;
    __syncthreads();

    // ---------- Fallback: exact 2-level radix select (statistically never) ----------
    if (M0 < KTOP || M0 > CAP) {
        for (int i = tid; i < NBINS; i += RTHREADS) s_hist[i] = 0;
        __syncthreads();
        for (int i = tid; i < NV4; i += RTHREADS) {
            float4 v = lg4[i];
            float vv[4] = {v.x, v.y, v.z, v.w};
            #pragma unroll
            for (int j = 0; j < 4; j++)
                atomicAdd(&s_hist[f2key(vv[j]) >> 21], 1u);
        }
        __syncthreads();
        if (tid == 0) {
            int acc = 0, b1 = 0;
            for (int bin = NBINS - 1; bin >= 0; bin--) {
                int c = (int)s_hist[bin];
                if (acc + c >= KTOP) { b1 = bin; break; }
                acc += c;
            }
            s_b1 = b1; s_gt = acc;
        }
        __syncthreads();
        const int b1 = s_b1;
        const int cnt_ge = s_gt + (int)s_hist[b1];

        if (cnt_ge <= CAP) {
            if (tid == 0) s_cnt = 0;
            __syncthreads();
            for (int i = tid; i < NV4; i += RTHREADS) {
                float4 v = lg4[i];
                float vv[4] = {v.x, v.y, v.z, v.w};
                #pragma unroll
                for (int j = 0; j < 4; j++) {
                    unsigned key = f2key(vv[j]);
                    if ((int)(key >> 21) >= b1) {
                        int pos = atomicAdd(&s_cnt, 1);
                        unsigned idx = (unsigned)(i * 4 + j);
                        s_pack[pos] = ((unsigned long long)key << 32)
                                      | (unsigned long long)(~idx);
                    }
                }
            }
            __syncthreads();
            M = s_cnt;
        } else {
            for (int i = tid; i < NBINS; i += RTHREADS) s_hist[i] = 0;
            __syncthreads();
            for (int i = tid; i < NV4; i += RTHREADS) {
                float4 v = lg4[i];
                float vv[4] = {v.x, v.y, v.z, v.w};
                #pragma unroll
                for (int j = 0; j < 4; j++) {
                    unsigned key = f2key(vv[j]);
                    if ((int)(key >> 21) == b1)
                        atomicAdd(&s_hist[(key >> 10) & 0x7FFu], 1u);
                }
            }
            __syncthreads();
            if (tid == 0) {
                int need = KTOP - s_gt;
                int acc = 0, b2 = 0;
                for (int bin = NBINS - 1; bin >= 0; bin--) {
                    int c = (int)s_hist[bin];
                    if (acc + c >= need) { b2 = bin; break; }
                    acc += c;
                }
                s_b2 = b2; s_cnt = 0;
            }
            __syncthreads();
            const int b2 = s_b2;
            for (int i = tid; i < NV4; i += RTHREADS) {
                float4 v = lg4[i];
                float vv[4] = {v.x, v.y, v.z, v.w};
                #pragma unroll
                for (int j = 0; j < 4; j++) {
                    unsigned key = f2key(vv[j]);
                    int hb = (int)(key >> 21);
                    bool take = (hb > b1) ||
                                (hb == b1 && (int)((key >> 10) & 0x7FFu) >= b2);
                    if (take) {
                        int pos = atomicAdd(&s_cnt, 1);
                        if (pos < CAP) {
                            unsigned idx = (unsigned)(i * 4 + j);
                            s_pack[pos] = ((unsigned long long)key << 32)
                                          | (unsigned long long)(~idx);
                        }
                    }
                }
            }
            __syncthreads();
            M = min(s_cnt, CAP);
        }
    }

    // pad one zero pack so the paired inner loop can read an even count
    // (zero pack sorts below every real pack -> never affects ranks)
    if (tid == 0 && M < CAP) s_pack[M] = 0ULL;
    __syncthreads();
    const int Mpair = (M + 1) >> 1;
    const ulonglong2* sp2 = (const ulonglong2*)s_pack;

    // ---------- Exact ranking (descending key, lower idx first on ties) ----------
    for (int i = tid; i < M; i += RTHREADS) {
        unsigned long long pi = s_pack[i];
        int r = 0;
        for (int j = 0; j < Mpair; j++) {
            ulonglong2 pj = sp2[j];
            r += (pj.x > pi) + (pj.y > pi);
        }
        if (r < KTOP) {
            unsigned key = (unsigned)(pi >> 32);
            unsigned idx = ~(unsigned)(pi & 0xFFFFFFFFull);
            int q = (int)(idx / CC);
            int c = (int)(idx % CC);
            float lv = key2f(key);
            float score = 1.0f / (1.0f + expf(-lv));

            size_t slot = (size_t)b * KTOP + r;
            out[LBL_OFF + slot] = (float)c;
            out[SCR_OFF + slot] = score;

            float4 bx = ((const float4*)boxes)[(size_t)b * QQ + q];
            float4 o;
            o.x = bx.x - 0.5f * bx.z;
            o.y = bx.y - 0.5f * bx.w;
            o.z = bx.x + 0.5f * bx.z;
            o.w = bx.y + 0.5f * bx.w;
            ((float4*)(out + BOX_OFF))[slot] = o;
        }
    }
}

extern "C" void kernel_launch(void* const* d_in, const int* in_sizes, int n_in,
                              void* d_out, int out_size)
{
    const float* logits = (const float*)d_in[0];
    const float* boxes  = (const float*)d_in[1];
    float* out = (float*)d_out;

    dim3 fgrid(SEGS, BATCH);
    filter_kernel<<<fgrid, FTHREADS>>>(logits);
    rank_kernel<<<BATCH, RTHREADS>>>(logits, boxes, out);
}

// round 11
// speedup vs baseline: 1.1461x; 1.1461x over previous
#include <cuda_runtime.h>
#include <cstdint>

// DETR-style postprocess (fused single launch, 4 segment-blocks per batch):
//   logits [256,1000,80] f32, boxes [256,1000,4] f32 (cxcywh)
//   -> labels [256,300], boxes_xyxy [256,300,4], scores [256,300]
// Output concatenated flat f32: labels | boxes | scores. (verified R3)

#define BATCH      256
#define QQ         1000
#define CC         80
#define NELEM      80000
#define NV4        20000      // float4 per batch
#define KTOP       300
#define CAP        3072       // ranking buffer (global cap <= 4*LOCCAP = 2048)
#define LOCCAP     512        // per-segment local candidate cap (mean ~125, sd ~11)
#define NBINS      2048
#define T_STATIC   2.5f

#define SEGS       4
#define NT         256        // threads per block
#define SEG_F4     (NV4 / SEGS)          // 5000
#define FULL_IT    4                     // 4 * 1024 float4
#define TGUARD     136                   // tail 904 = 3*256 + 136

#define LBL_OFF    0
#define BOX_OFF    (BATCH * KTOP)            // 76800
#define SCR_OFF    (BATCH * KTOP * 5)        // 384000

// Global scratch (zero-init at module load; ranking block resets per replay)
__device__ unsigned long long g_pack[BATCH][CAP];
__device__ int g_cnt[BATCH];
__device__ int g_done[BATCH];
__device__ int g_ovf[BATCH];

__device__ __forceinline__ unsigned f2key(float x) {
    unsigned bb = __float_as_uint(x);
    return (bb & 0x80000000u) ? ~bb : (bb | 0x80000000u);
}
__device__ __forceinline__ float key2f(unsigned k) {
    unsigned bb = (k & 0x80000000u) ? (k & 0x7FFFFFFFu) : ~k;
    return __uint_as_float(bb);
}

__global__ __launch_bounds__(NT, 7)
void postproc_kernel(const float* __restrict__ logits,
                     const float* __restrict__ boxes,
                     float* __restrict__ out)
{
    // s_pack serves three roles in sequence:
    //   stream: local candidate buffer [0..LOCCAP)
    //   fallback: radix histogram overlays first 8KB (pack filled only after
    //             b1/gt/cg/b2 are extracted into scalars)
    //   rank: full candidate list [0..M)
    __shared__ __align__(16) unsigned long long s_pack[CAP];
    __shared__ int s_cnt, s_base, s_rank, s_M, s_ovf;
    __shared__ int s_b1, s_gt, s_cg, s_b2;

    const int b   = blockIdx.y;
    const int seg = blockIdx.x;
    const int tid = threadIdx.x;
    const float4* lg4 = (const float4*)(logits + (size_t)b * NELEM);
    const int base0 = seg * SEG_F4;

    if (tid == 0) s_cnt = 0;
    __syncthreads();

    // ---------------- stream this segment (MLP=4 front-batched) ----------------
    #pragma unroll 1
    for (int it = 0; it < FULL_IT; it++) {
        int base = base0 + it * (4 * NT) + tid;
        float4 v0 = lg4[base];
        float4 v1 = lg4[base + NT];
        float4 v2 = lg4[base + 2 * NT];
        float4 v3 = lg4[base + 3 * NT];
        float vv[16] = {v0.x, v0.y, v0.z, v0.w,  v1.x, v1.y, v1.z, v1.w,
                        v2.x, v2.y, v2.z, v2.w,  v3.x, v3.y, v3.z, v3.w};
        #pragma unroll
        for (int k = 0; k < 16; k++) {
            if (vv[k] > T_STATIC) {
                int pos = atomicAdd(&s_cnt, 1);
                if (pos < LOCCAP) {
                    unsigned idx = (unsigned)((base + (k >> 2) * NT) * 4 + (k & 3));
                    s_pack[pos] = ((unsigned long long)f2key(vv[k]) << 32)
                                  | (unsigned long long)(~idx);
                }
            }
        }
    }
    {   // tail: 904 float4
        int base = base0 + FULL_IT * (4 * NT) + tid;
        float4 v0 = lg4[base];
        float4 v1 = lg4[base + NT];
        float4 v2 = lg4[base + 2 * NT];
        float4 v3 = make_float4(-1e30f, -1e30f, -1e30f, -1e30f);
        if (tid < TGUARD) v3 = lg4[base + 3 * NT];
        float vv[16] = {v0.x, v0.y, v0.z, v0.w,  v1.x, v1.y, v1.z, v1.w,
                        v2.x, v2.y, v2.z, v2.w,  v3.x, v3.y, v3.z, v3.w};
        #pragma unroll
        for (int k = 0; k < 16; k++) {
            if (vv[k] > T_STATIC) {
                int pos = atomicAdd(&s_cnt, 1);
                if (pos < LOCCAP) {
                    unsigned idx = (unsigned)((base + (k >> 2) * NT) * 4 + (k & 3));
                    s_pack[pos] = ((unsigned long long)f2key(vv[k]) << 32)
                                  | (unsigned long long)(~idx);
                }
            }
        }
    }
    __syncthreads();

    // ---------------- publish candidates, signal done ----------------
    const int cnt  = s_cnt;
    const int my_n = min(cnt, LOCCAP);
    if (tid == 0) {
        s_base = atomicAdd(&g_cnt[b], my_n);
        if (cnt > LOCCAP) atomicExch(&g_ovf[b], 1);
    }
    __syncthreads();
    const int gbase = s_base;
    for (int i = tid; i < my_n; i += NT)
        g_pack[b][gbase + i] = s_pack[i];
    __threadfence();
    __syncthreads();
    if (tid == 0) {
        int old = atomicAdd(&g_done[b], 1);
        s_rank = (old == SEGS - 1);
    }
    __syncthreads();
    if (!s_rank) return;

    // ---------------- last block of this batch: rank + output ----------------
    if (tid == 0) {
        s_M   = atomicAdd(&g_cnt[b], 0);
        s_ovf = atomicAdd(&g_ovf[b], 0);
    }
    __syncthreads();
    int M = s_M;

    if (M >= KTOP && !s_ovf) {
        for (int i = tid; i < M; i += NT)
            s_pack[i] = __ldcg(&g_pack[b][i]);
        __syncthreads();
    } else {
        // ---------- exact 2-level radix fallback over the full batch ----------
        unsigned* s_hist = (unsigned*)s_pack;   // overlay (see header comment)
        for (int i = tid; i < NBINS; i += NT) s_hist[i] = 0;
        __syncthreads();
        for (int i = tid; i < NV4; i += NT) {
            float4 v = lg4[i];
            float vv[4] = {v.x, v.y, v.z, v.w};
            #pragma unroll
            for (int j = 0; j < 4; j++)
                atomicAdd(&s_hist[f2key(vv[j]) >> 21], 1u);
        }
        __syncthreads();
        if (tid == 0) {
            int acc = 0, b1 = 0;
            for (int bin = NBINS - 1; bin >= 0; bin--) {
                int c = (int)s_hist[bin];
                if (acc + c >= KTOP) { b1 = bin; break; }
                acc += c;
            }
            s_b1 = b1; s_gt = acc; s_cg = acc + (int)s_hist[b1];
            s_cnt = 0;
        }
        __syncthreads();
        const int b1 = s_b1;

        if (s_cg <= CAP) {
            __syncthreads();   // all reads of hist complete before pack fill
            for (int i = tid; i < NV4; i += NT) {
                float4 v = lg4[i];
                float vv[4] = {v.x, v.y, v.z, v.w};
                #pragma unroll
                for (int j = 0; j < 4; j++) {
                    unsigned key = f2key(vv[j]);
                    if ((int)(key >> 21) >= b1) {
                        int pos = atomicAdd(&s_cnt, 1);
                        unsigned idx = (unsigned)(i * 4 + j);
                        s_pack[pos] = ((unsigned long long)key << 32)
                                      | (unsigned long long)(~idx);
                    }
                }
            }
            __syncthreads();
            M = s_cnt;
        } else {
            for (int i = tid; i < NBINS; i += NT) s_hist[i] = 0;
            __syncthreads();
            for (int i = tid; i < NV4; i += NT) {
                float4 v = lg4[i];
                float vv[4] = {v.x, v.y, v.z, v.w};
                #pragma unroll
                for (int j = 0; j < 4; j++) {
                    unsigned key = f2key(vv[j]);
                    if ((int)(key >> 21) == b1)
                        atomicAdd(&s_hist[(key >> 10) & 0x7FFu], 1u);
                }
            }
            __syncthreads();
            if (tid == 0) {
                int need = KTOP - s_gt;
                int acc = 0, b2 = 0;
                for (int bin = NBINS - 1; bin >= 0; bin--) {
                    int c = (int)s_hist[bin];
                    if (acc + c >= need) { b2 = bin; break; }
                    acc += c;
                }
                s_b2 = b2; s_cnt = 0;
            }
            __syncthreads();
            const int b2 = s_b2;
            for (int i = tid; i < NV4; i += NT) {
                float4 v = lg4[i];
                float vv[4] = {v.x, v.y, v.z, v.w};
                #pragma unroll
                for (int j = 0; j < 4; j++) {
                    unsigned key = f2key(vv[j]);
                    int hb = (int)(key >> 21);
                    bool take = (hb > b1) ||
                                (hb == b1 && (int)((key >> 10) & 0x7FFu) >= b2);
                    if (take) {
                        int pos = atomicAdd(&s_cnt, 1);
                        if (pos < CAP) {
                            unsigned idx = (unsigned)(i * 4 + j);
                            s_pack[pos] = ((unsigned long long)key << 32)
                                          | (unsigned long long)(~idx);
                        }
                    }
                }
            }
            __syncthreads();
            M = min(s_cnt, CAP);
        }
    }

    // zero pad (sorts below all real packs -> never affects ranks)
    if (tid == 0 && M < CAP) s_pack[M] = 0ULL;
    __syncthreads();
    const int Mpair = (M + 1) >> 1;
    const ulonglong2* sp2 = (const ulonglong2*)s_pack;

    // exact ranking: descending key, lower idx first on ties
    for (int i = tid; i < M; i += NT) {
        unsigned long long pi = s_pack[i];
        int r = 0;
        for (int j = 0; j < Mpair; j++) {
            ulonglong2 pj = sp2[j];
            r += (pj.x > pi) + (pj.y > pi);
        }
        if (r < KTOP) {
            unsigned key = (unsigned)(pi >> 32);
            unsigned idx = ~(unsigned)(pi & 0xFFFFFFFFull);
            int q = (int)(idx / CC);
            int c = (int)(idx % CC);
            float lv = key2f(key);
            float score = 1.0f / (1.0f + expf(-lv));

            size_t slot = (size_t)b * KTOP + r;
            out[LBL_OFF + slot] = (float)c;
            out[SCR_OFF + slot] = score;

            float4 bx = ((const float4*)boxes)[(size_t)b * QQ + q];
            float4 o;
            o.x = bx.x - 0.5f * bx.z;
            o.y = bx.y - 0.5f * bx.w;
            o.z = bx.x + 0.5f * bx.z;
            o.w = bx.y + 0.5f * bx.w;
            ((float4*)(out + BOX_OFF))[slot] = o;
        }
    }

    __syncthreads();
    if (tid == 0) {           // reset for next graph replay
        g_cnt[b]  = 0;
        g_done[b] = 0;
        g_ovf[b]  = 0;
    }
}

extern "C" void kernel_launch(void* const* d_in, const int* in_sizes, int n_in,
                              void* d_out, int out_size)
{
    const float* logits = (const float*)d_in[0];
    const float* boxes  = (const float*)d_in[1];
    float* out = (float*)d_out;

    dim3 grid(SEGS, BATCH);
    postproc_kernel<<<grid, NT>>>(logits, boxes, out);
}